// round 6
// baseline (speedup 1.0000x reference)
#include <cuda_runtime.h>

// Kannala-Brandt fisheye round-trip, fully collapsed:
//   t solves t*d(t) = ru  (2 quasi-Newton steps, rcp(fp)~=2-fp)
//   output = sinc(t) * (pixel - center) + center
// (d(t)*sin(t)/ru == sin(t)/t at the Newton fixed point; focal lengths cancel.)
// sinc via degree-8 Taylor in t^2: |err| <= 4.7e-7 for t <= 1.35 — removes the
// sin and rcp MUFU ops entirely; only sqrtf remains.
//
// 8 points per thread with 4 front-batched LDG.128: ~16KB of in-flight loads
// per SM, matching B300's latency-bandwidth product (27 B/cyc x ~600 cyc).

#define CX 640.0f
#define CY 480.0f
#define EPS 1e-5f

struct KParams { float k0, k1, k2, k3, k4, k0e, d1, d2, d3, d4, rfx, rfy; };

__device__ __forceinline__ float2 kb_point(float px, float py, const KParams& P)
{
    float dx = px - CX;
    float dy = py - CY;
    float mx = dx * P.rfx;
    float my = dy * P.rfy;
    float q  = fmaf(mx, mx, fmaf(my, my, 1e-30f));
    float ru = sqrtf(q);

    // quasi-Newton on t*d(t) = ru
    float t = ru;
#pragma unroll
    for (int it = 0; it < 2; ++it) {
        float p  = ((((P.k4 * t + P.k3) * t + P.k2) * t + P.k1) * t + P.k0);
        float r  = fmaf(p, t, -ru);                                   // residual
        float fp = (((P.d4 * t + P.d3) * t + P.d2) * t + P.d1) * t + P.k0e;
        t = fmaf(-2.0f, r, fmaf(r, fp, t));                           // t -= r*(2-fp)
    }

    // w = sinc(t), Taylor in t^2 (exact to ~5e-7 on [0, 1.35])
    float t2 = t * t;
    float w = fmaf(t2, fmaf(t2, fmaf(t2, fmaf(t2, 2.7557319e-6f, -1.9841270e-4f),
                                     8.3333333e-3f), -1.6666667e-1f), 1.0f);

    return make_float2(fmaf(w, dx, CX), fmaf(w, dy, CY));
}

__global__ void kb_roundtrip_kernel(const float4* __restrict__ in4,
                                    const float2* __restrict__ in2,
                                    const float*  __restrict__ kvec,
                                    const float*  __restrict__ fx_p,
                                    const float*  __restrict__ fy_p,
                                    float4*       __restrict__ out4,
                                    float2*       __restrict__ out2,
                                    int n_octs, int n_tail_pts)
{
    int i = blockIdx.x * blockDim.x + threadIdx.x;

    KParams P;
    P.k0 = __ldg(&kvec[0]); P.k1 = __ldg(&kvec[1]); P.k2 = __ldg(&kvec[2]);
    P.k3 = __ldg(&kvec[3]); P.k4 = __ldg(&kvec[4]);
    P.k0e = P.k0 + EPS;
    P.d1 = 2.0f * P.k1; P.d2 = 3.0f * P.k2; P.d3 = 4.0f * P.k3; P.d4 = 5.0f * P.k4;
    P.rfx = __fdividef(1.0f, __ldg(fx_p));
    P.rfy = __fdividef(1.0f, __ldg(fy_p));

    if (i < n_octs) {
        // 8 points per thread: 4 x LDG.128 issued back-to-back (MLP_p1 = 4)
        float4 a = in4[4 * i];
        float4 b = in4[4 * i + 1];
        float4 c = in4[4 * i + 2];
        float4 d = in4[4 * i + 3];

        float2 r0 = kb_point(a.x, a.y, P);
        float2 r1 = kb_point(a.z, a.w, P);
        float2 r2 = kb_point(b.x, b.y, P);
        float2 r3 = kb_point(b.z, b.w, P);
        float2 r4 = kb_point(c.x, c.y, P);
        float2 r5 = kb_point(c.z, c.w, P);
        float2 r6 = kb_point(d.x, d.y, P);
        float2 r7 = kb_point(d.z, d.w, P);

        out4[4 * i]     = make_float4(r0.x, r0.y, r1.x, r1.y);
        out4[4 * i + 1] = make_float4(r2.x, r2.y, r3.x, r3.y);
        out4[4 * i + 2] = make_float4(r4.x, r4.y, r5.x, r5.y);
        out4[4 * i + 3] = make_float4(r6.x, r6.y, r7.x, r7.y);
    }
    // tail (none for N = 4194304; kept for generality)
    if (n_tail_pts && i == 0) {
        for (int j = 0; j < n_tail_pts; ++j) {
            int idx = 8 * n_octs + j;
            float2 p = in2[idx];
            out2[idx] = kb_point(p.x, p.y, P);
        }
    }
}

extern "C" void kernel_launch(void* const* d_in, const int* in_sizes, int n_in,
                              void* d_out, int out_size)
{
    const float* uv = (const float*)d_in[0];   // [N,2] fp32
    const float* kv = (const float*)d_in[1];   // k_vector [5]
    const float* fx = (const float*)d_in[2];
    const float* fy = (const float*)d_in[3];

    int n      = in_sizes[0] / 2;
    int n_octs = n / 8;
    int n_tail = n - 8 * n_octs;

    const int threads = 256;
    int work   = n_octs > 0 ? n_octs : 1;
    int blocks = (work + threads - 1) / threads;

    kb_roundtrip_kernel<<<blocks, threads>>>(
        (const float4*)uv, (const float2*)uv, kv, fx, fy,
        (float4*)d_out, (float2*)d_out, n_octs, n_tail);
}

// round 8
// speedup vs baseline: 1.1552x; 1.1552x over previous
#include <cuda_runtime.h>

// Kannala-Brandt fisheye round-trip, minimal form.
//
//   ru = |(px-cx)/fx, (py-cy)/fy|
//   solve t*d(t) = ru by plain fixed-point:  t <- t - (t*d(t) - ru)
//       contraction |1 - d/dt[t*d(t)]| <= 0.011 on [0,1.35]; e0 ~ 0.01,
//       three iterations -> |t - t*| ~ 1.3e-8.
//   output = sinc(t) * (pixel - center) + center
//       (d(t)*sin(t)/ru == sin(t)/t at the fixed point; focal lengths cancel)
//   sinc via degree-8 Taylor in t^2 (|err| <= 5e-7 on [0,1.35]).
//   ru = q * rsqrt(q): one MUFU.RSQ instead of IEEE sqrt.rn lowering.
//
// R7 bug fixed: the update is written as residual-then-subtract; the previous
// hand-fused fma form dropped the leading t (ru - p*t instead of t - p*t + ru).

#define CX 640.0f
#define CY 480.0f

struct KParams { float k0, k1, k2, k3, k4, rfx, rfy; };

__device__ __forceinline__ float2 kb_point(float px, float py, const KParams& P)
{
    float dx = px - CX;
    float dy = py - CY;
    float mx = dx * P.rfx;
    float my = dy * P.rfy;
    float q  = fmaf(mx, mx, fmaf(my, my, 1e-30f));
    float ru = q * rsqrtf(q);           // sqrt(q) via MUFU.RSQ + 1 mul

    // fixed-point iteration on t*d(t) = ru (3 steps)
    float t = ru;
#pragma unroll
    for (int it = 0; it < 3; ++it) {
        float p = ((((P.k4 * t + P.k3) * t + P.k2) * t + P.k1) * t + P.k0);
        float r = fmaf(p, t, -ru);      // residual t*d(t) - ru
        t = t - r;
    }

    // w = sinc(t), Taylor in t^2
    float t2 = t * t;
    float w = fmaf(t2, fmaf(t2, fmaf(t2, fmaf(t2, 2.7557319e-6f, -1.9841270e-4f),
                                     8.3333333e-3f), -1.6666667e-1f), 1.0f);

    return make_float2(fmaf(w, dx, CX), fmaf(w, dy, CY));
}

__global__ void __launch_bounds__(256)
kb_roundtrip_kernel(const float4* __restrict__ in4,
                    const float2* __restrict__ in2,
                    const float*  __restrict__ kvec,
                    const float*  __restrict__ fx_p,
                    const float*  __restrict__ fy_p,
                    float4*       __restrict__ out4,
                    float2*       __restrict__ out2,
                    int n_pairs, int n_tail_pts)
{
    int i = blockIdx.x * blockDim.x + threadIdx.x;

    KParams P;
    P.k0 = __ldg(&kvec[0]); P.k1 = __ldg(&kvec[1]); P.k2 = __ldg(&kvec[2]);
    P.k3 = __ldg(&kvec[3]); P.k4 = __ldg(&kvec[4]);
    P.rfx = __fdividef(1.0f, __ldg(fx_p));
    P.rfy = __fdividef(1.0f, __ldg(fy_p));

    if (i < n_pairs) {
        float4 p = in4[i];
        float2 a = kb_point(p.x, p.y, P);
        float2 b = kb_point(p.z, p.w, P);
        out4[i] = make_float4(a.x, a.y, b.x, b.y);
    }
    // tail (none for N = 4194304; kept for generality)
    if (n_tail_pts && i == 0) {
        for (int j = 0; j < n_tail_pts; ++j) {
            int idx = 2 * n_pairs + j;
            float2 p = in2[idx];
            out2[idx] = kb_point(p.x, p.y, P);
        }
    }
}

extern "C" void kernel_launch(void* const* d_in, const int* in_sizes, int n_in,
                              void* d_out, int out_size)
{
    const float* uv = (const float*)d_in[0];   // [N,2] fp32
    const float* kv = (const float*)d_in[1];   // k_vector [5]
    const float* fx = (const float*)d_in[2];
    const float* fy = (const float*)d_in[3];

    int n       = in_sizes[0] / 2;
    int n_pairs = n / 2;
    int n_tail  = n - 2 * n_pairs;

    const int threads = 256;
    int work   = n_pairs > 0 ? n_pairs : 1;
    int blocks = (work + threads - 1) / threads;

    kb_roundtrip_kernel<<<blocks, threads>>>(
        (const float4*)uv, (const float2*)uv, kv, fx, fy,
        (float4*)d_out, (float2*)d_out, n_pairs, n_tail);
}

// round 9
// speedup vs baseline: 1.3170x; 1.1400x over previous
#include <cuda_runtime.h>

// Kannala-Brandt fisheye round-trip — persistent grid + software pipeline.
//
// Math (validated in R8, rel_err 6.1e-6 vs 1e-3 tolerance):
//   ru = |(px-cx)/fx, (py-cy)/fy|        (sqrt via MUFU.RSQ: ru = q*rsqrt(q))
//   t: 3 fixed-point steps of t <- t - (t*d(t) - ru)   (contraction 0.011)
//   out = sinc(t)*(pixel-center) + center   (sinc = deg-8 Taylor in t^2;
//        d(t)*sin(t)/ru == sin(t)/t at the fixed point, focal lengths cancel)
//
// Structure change: R3-R8 showed duration pinned at ~14us while per-point ops
// halved — latency exposure at each of ~7 CTA waves was the invariant. Now:
// one resident wave (148 SMs x 8 CTAs), each thread grid-strides ~7 pairs and
// prefetches the next float4 before computing the current one, keeping one
// load in flight per warp at all times.

#define CX 640.0f
#define CY 480.0f

struct KParams { float k0, k1, k2, k3, k4, rfx, rfy; };

__device__ __forceinline__ float2 kb_point(float px, float py, const KParams& P)
{
    float dx = px - CX;
    float dy = py - CY;
    float mx = dx * P.rfx;
    float my = dy * P.rfy;
    float q  = fmaf(mx, mx, fmaf(my, my, 1e-30f));
    float ru = q * rsqrtf(q);

    float t = ru;
#pragma unroll
    for (int it = 0; it < 3; ++it) {
        float p = ((((P.k4 * t + P.k3) * t + P.k2) * t + P.k1) * t + P.k0);
        float r = fmaf(p, t, -ru);
        t = t - r;
    }

    float t2 = t * t;
    float w = fmaf(t2, fmaf(t2, fmaf(t2, fmaf(t2, 2.7557319e-6f, -1.9841270e-4f),
                                     8.3333333e-3f), -1.6666667e-1f), 1.0f);

    return make_float2(fmaf(w, dx, CX), fmaf(w, dy, CY));
}

__global__ void __launch_bounds__(256)
kb_roundtrip_kernel(const float4* __restrict__ in4,
                    const float2* __restrict__ in2,
                    const float*  __restrict__ kvec,
                    const float*  __restrict__ fx_p,
                    const float*  __restrict__ fy_p,
                    float4*       __restrict__ out4,
                    float2*       __restrict__ out2,
                    int n_pairs, int n_tail_pts)
{
    const int stride = gridDim.x * blockDim.x;
    int i = blockIdx.x * blockDim.x + threadIdx.x;

    KParams P;
    P.k0 = __ldg(&kvec[0]); P.k1 = __ldg(&kvec[1]); P.k2 = __ldg(&kvec[2]);
    P.k3 = __ldg(&kvec[3]); P.k4 = __ldg(&kvec[4]);
    P.rfx = __fdividef(1.0f, __ldg(fx_p));
    P.rfy = __fdividef(1.0f, __ldg(fy_p));

    // software-pipelined grid-stride loop: next load in flight during compute
    bool valid = i < n_pairs;
    float4 cur = make_float4(0.f, 0.f, 0.f, 0.f);
    if (valid) cur = in4[i];

    while (valid) {
        int  inext  = i + stride;
        bool vnext  = inext < n_pairs;
        float4 nxt  = make_float4(0.f, 0.f, 0.f, 0.f);
        if (vnext) nxt = in4[inext];          // prefetch next tile

        float2 a = kb_point(cur.x, cur.y, P);
        float2 b = kb_point(cur.z, cur.w, P);
        out4[i] = make_float4(a.x, a.y, b.x, b.y);

        cur = nxt; i = inext; valid = vnext;
    }

    // tail (none for N = 4194304; kept for generality)
    if (n_tail_pts && blockIdx.x == 0 && threadIdx.x == 0) {
        for (int j = 0; j < n_tail_pts; ++j) {
            int idx = 2 * n_pairs + j;
            float2 p = in2[idx];
            out2[idx] = kb_point(p.x, p.y, P);
        }
    }
}

extern "C" void kernel_launch(void* const* d_in, const int* in_sizes, int n_in,
                              void* d_out, int out_size)
{
    const float* uv = (const float*)d_in[0];   // [N,2] fp32
    const float* kv = (const float*)d_in[1];   // k_vector [5]
    const float* fx = (const float*)d_in[2];
    const float* fy = (const float*)d_in[3];

    int n       = in_sizes[0] / 2;
    int n_pairs = n / 2;
    int n_tail  = n - 2 * n_pairs;

    const int threads = 256;
    // one resident wave: 148 SMs x 8 CTAs of 256 threads (2048 thr/SM)
    int blocks = 148 * 8;
    int need   = (n_pairs + threads - 1) / threads;
    if (need < blocks) blocks = need > 0 ? need : 1;

    kb_roundtrip_kernel<<<blocks, threads>>>(
        (const float4*)uv, (const float2*)uv, kv, fx, fy,
        (float4*)d_out, (float2*)d_out, n_pairs, n_tail);
}

// round 10
// speedup vs baseline: 1.3202x; 1.0025x over previous
#include <cuda_runtime.h>

// Kannala-Brandt fisheye round-trip — persistent grid, 2-deep software pipeline.
//
// Math (validated R8/R9, rel_err ~6e-6 vs 1e-3 tolerance):
//   ru = |(px-cx)/fx, (py-cy)/fy|      (sqrt via MUFU.RSQ: ru = q*rsqrt(q))
//   t:  2 fixed-point steps of t <- t - (t*d(t) - ru)
//       (contraction |1-f'| <= 0.011, e0 <= 0.010 -> e2 ~ 1.2e-6 in t,
//        ~5e-7 rel in the output weight)
//   out = sinc(t)*(pixel-center) + center   (deg-8 Taylor sinc;
//        d(t)*sin(t)/ru == sin(t)/t at the fixed point, focal lengths cancel)
//
// Pipeline: one resident wave (148x8 CTAs); each thread grid-strides with TWO
// float4 loads in flight (rotating 2-stage buffer) -> ~16KB in-flight per SM,
// matching B300's DRAM latency-bandwidth product. R9 (depth 1) left issue at
// 61% with correlated long-scoreboard stalls; depth 2 converts them to issue.

#define CX 640.0f
#define CY 480.0f

struct KParams { float k0, k1, k2, k3, k4, rfx, rfy; };

__device__ __forceinline__ float2 kb_point(float px, float py, const KParams& P)
{
    float dx = px - CX;
    float dy = py - CY;
    float mx = dx * P.rfx;
    float my = dy * P.rfy;
    float q  = fmaf(mx, mx, fmaf(my, my, 1e-30f));
    float ru = q * rsqrtf(q);

    float t = ru;
#pragma unroll
    for (int it = 0; it < 2; ++it) {
        float p = ((((P.k4 * t + P.k3) * t + P.k2) * t + P.k1) * t + P.k0);
        float r = fmaf(p, t, -ru);
        t = t - r;
    }

    float t2 = t * t;
    float w = fmaf(t2, fmaf(t2, fmaf(t2, fmaf(t2, 2.7557319e-6f, -1.9841270e-4f),
                                     8.3333333e-3f), -1.6666667e-1f), 1.0f);

    return make_float2(fmaf(w, dx, CX), fmaf(w, dy, CY));
}

__global__ void __launch_bounds__(256)
kb_roundtrip_kernel(const float4* __restrict__ in4,
                    const float2* __restrict__ in2,
                    const float*  __restrict__ kvec,
                    const float*  __restrict__ fx_p,
                    const float*  __restrict__ fy_p,
                    float4*       __restrict__ out4,
                    float2*       __restrict__ out2,
                    int n_pairs, int n_tail_pts)
{
    const int stride = gridDim.x * blockDim.x;
    int i = blockIdx.x * blockDim.x + threadIdx.x;

    KParams P;
    P.k0 = __ldg(&kvec[0]); P.k1 = __ldg(&kvec[1]); P.k2 = __ldg(&kvec[2]);
    P.k3 = __ldg(&kvec[3]); P.k4 = __ldg(&kvec[4]);
    P.rfx = __fdividef(1.0f, __ldg(fx_p));
    P.rfy = __fdividef(1.0f, __ldg(fy_p));

    // 2-deep software pipeline over the grid-stride loop
    float4 buf0 = make_float4(0.f, 0.f, 0.f, 0.f);
    float4 buf1 = make_float4(0.f, 0.f, 0.f, 0.f);
    bool v0 = i < n_pairs;
    bool v1 = (i + stride) < n_pairs;
    if (v0) buf0 = in4[i];
    if (v1) buf1 = in4[i + stride];

    while (v0) {
        int  i2 = i + 2 * stride;
        bool v2 = i2 < n_pairs;
        float4 nxt = make_float4(0.f, 0.f, 0.f, 0.f);
        if (v2) nxt = in4[i2];                // keep 2 loads in flight

        float2 a = kb_point(buf0.x, buf0.y, P);
        float2 b = kb_point(buf0.z, buf0.w, P);
        out4[i] = make_float4(a.x, a.y, b.x, b.y);

        buf0 = buf1; buf1 = nxt;
        i += stride; v0 = v1; v1 = v2;
    }

    // tail (none for N = 4194304; kept for generality)
    if (n_tail_pts && blockIdx.x == 0 && threadIdx.x == 0) {
        for (int j = 0; j < n_tail_pts; ++j) {
            int idx = 2 * n_pairs + j;
            float2 p = in2[idx];
            out2[idx] = kb_point(p.x, p.y, P);
        }
    }
}

extern "C" void kernel_launch(void* const* d_in, const int* in_sizes, int n_in,
                              void* d_out, int out_size)
{
    const float* uv = (const float*)d_in[0];   // [N,2] fp32
    const float* kv = (const float*)d_in[1];   // k_vector [5]
    const float* fx = (const float*)d_in[2];
    const float* fy = (const float*)d_in[3];

    int n       = in_sizes[0] / 2;
    int n_pairs = n / 2;
    int n_tail  = n - 2 * n_pairs;

    const int threads = 256;
    int blocks = 148 * 8;                      // one resident wave
    int need   = (n_pairs + threads - 1) / threads;
    if (need < blocks) blocks = need > 0 ? need : 1;

    kb_roundtrip_kernel<<<blocks, threads>>>(
        (const float4*)uv, (const float2*)uv, kv, fx, fy,
        (float4*)d_out, (float2*)d_out, n_pairs, n_tail);
}

// round 11
// speedup vs baseline: 1.5627x; 1.1837x over previous
#include <cuda_runtime.h>

// Kannala-Brandt fisheye round-trip — exact-division specialization.
//
// Math (validated R8-R10, rel_err ~6.2e-6 vs 1e-3 tolerance):
//   ru = |(px-cx)/fx, (py-cy)/fy|      (sqrt via MUFU.RSQ: ru = q*rsqrt(q))
//   t:  2 fixed-point steps of t <- t - (t*d(t) - ru)
//   out = sinc(t)*(pixel-center) + center   (deg-8 Taylor sinc;
//        d(t)*sin(t)/ru == sin(t)/t at the fixed point, focal lengths cancel)
//
// Structure: n_pairs = 2^21 divides a 1024x256 grid exactly -> specialized
// kernel with compile-time stride, 8 unrolled iterations, ZERO bounds checks
// or predicates (R10's alu pipe hit 21% on pipeline bookkeeping). All 8
// LDG.128 issued up front from one base register + immediate offsets.

#define CX 640.0f
#define CY 480.0f

#define XBLOCKS 1024
#define XTHREADS 256
#define XSTRIDE (XBLOCKS * XTHREADS)     // 262144 pairs, compile-time

struct KParams { float k0, k1, k2, k3, k4, rfx, rfy; };

__device__ __forceinline__ KParams load_params(const float* kvec,
                                               const float* fx_p,
                                               const float* fy_p)
{
    KParams P;
    P.k0 = __ldg(&kvec[0]); P.k1 = __ldg(&kvec[1]); P.k2 = __ldg(&kvec[2]);
    P.k3 = __ldg(&kvec[3]); P.k4 = __ldg(&kvec[4]);
    P.rfx = __fdividef(1.0f, __ldg(fx_p));
    P.rfy = __fdividef(1.0f, __ldg(fy_p));
    return P;
}

__device__ __forceinline__ float2 kb_point(float px, float py, const KParams& P)
{
    float dx = px - CX;
    float dy = py - CY;
    float mx = dx * P.rfx;
    float my = dy * P.rfy;
    float q  = fmaf(mx, mx, fmaf(my, my, 1e-30f));
    float ru = q * rsqrtf(q);

    float t = ru;
#pragma unroll
    for (int it = 0; it < 2; ++it) {
        float p = ((((P.k4 * t + P.k3) * t + P.k2) * t + P.k1) * t + P.k0);
        float r = fmaf(p, t, -ru);
        t = t - r;
    }

    float t2 = t * t;
    float w = fmaf(t2, fmaf(t2, fmaf(t2, fmaf(t2, 2.7557319e-6f, -1.9841270e-4f),
                                     8.3333333e-3f), -1.6666667e-1f), 1.0f);

    return make_float2(fmaf(w, dx, CX), fmaf(w, dy, CY));
}

// ---- specialized: n_pairs == XSTRIDE * ITERS exactly ----
template <int ITERS>
__global__ void __launch_bounds__(XTHREADS)
kb_exact_kernel(const float4* __restrict__ in4,
                const float*  __restrict__ kvec,
                const float*  __restrict__ fx_p,
                const float*  __restrict__ fy_p,
                float4*       __restrict__ out4)
{
    const int base = blockIdx.x * XTHREADS + threadIdx.x;
    const KParams P = load_params(kvec, fx_p, fy_p);

    float4 v[ITERS];
#pragma unroll
    for (int k = 0; k < ITERS; ++k)
        v[k] = in4[base + k * XSTRIDE];       // 8 independent LDG.128

#pragma unroll
    for (int k = 0; k < ITERS; ++k) {
        float2 a = kb_point(v[k].x, v[k].y, P);
        float2 b = kb_point(v[k].z, v[k].w, P);
        out4[base + k * XSTRIDE] = make_float4(a.x, a.y, b.x, b.y);
    }
}

// ---- generic fallback (R10 structure) ----
__global__ void __launch_bounds__(256)
kb_generic_kernel(const float4* __restrict__ in4,
                  const float2* __restrict__ in2,
                  const float*  __restrict__ kvec,
                  const float*  __restrict__ fx_p,
                  const float*  __restrict__ fy_p,
                  float4*       __restrict__ out4,
                  float2*       __restrict__ out2,
                  int n_pairs, int n_tail_pts)
{
    const int stride = gridDim.x * blockDim.x;
    int i = blockIdx.x * blockDim.x + threadIdx.x;
    const KParams P = load_params(kvec, fx_p, fy_p);

    for (; i < n_pairs; i += stride) {
        float4 p = in4[i];
        float2 a = kb_point(p.x, p.y, P);
        float2 b = kb_point(p.z, p.w, P);
        out4[i] = make_float4(a.x, a.y, b.x, b.y);
    }

    if (n_tail_pts && blockIdx.x == 0 && threadIdx.x == 0) {
        for (int j = 0; j < n_tail_pts; ++j) {
            int idx = 2 * n_pairs + j;
            float2 p = in2[idx];
            out2[idx] = kb_point(p.x, p.y, P);
        }
    }
}

extern "C" void kernel_launch(void* const* d_in, const int* in_sizes, int n_in,
                              void* d_out, int out_size)
{
    const float* uv = (const float*)d_in[0];   // [N,2] fp32
    const float* kv = (const float*)d_in[1];   // k_vector [5]
    const float* fx = (const float*)d_in[2];
    const float* fy = (const float*)d_in[3];

    int n       = in_sizes[0] / 2;
    int n_pairs = n / 2;
    int n_tail  = n - 2 * n_pairs;

    if (n_tail == 0 && n_pairs == XSTRIDE * 8) {
        // bench shape: N = 4194304 -> n_pairs = 2^21 = 8 * 262144
        kb_exact_kernel<8><<<XBLOCKS, XTHREADS>>>(
            (const float4*)uv, kv, fx, fy, (float4*)d_out);
    } else {
        const int threads = 256;
        int blocks = 148 * 8;
        int need   = (n_pairs + threads - 1) / threads;
        if (need < blocks) blocks = need > 0 ? need : 1;
        kb_generic_kernel<<<blocks, threads>>>(
            (const float4*)uv, (const float2*)uv, kv, fx, fy,
            (float4*)d_out, (float2*)d_out, n_pairs, n_tail);
    }
}

// round 12
// speedup vs baseline: 1.6000x; 1.0239x over previous
#include <cuda_runtime.h>

// Kannala-Brandt fisheye round-trip — exact-division, fine-grained.
//
// Math (validated R8-R11, rel_err 6.2e-6 vs 1e-3 tolerance):
//   ru = |(px-cx)/fx, (py-cy)/fy|      (sqrt via MUFU.RSQ: ru = q*rsqrt(q))
//   t:  2 fixed-point steps of t <- t - (t*d(t) - ru)
//   out = sinc(t)*(pixel-center) + center   (deg-8 Taylor sinc;
//        d(t)*sin(t)/ru == sin(t)/t at the fixed point, focal lengths cancel)
//
// R11 -> R12: ITERS 8 -> 4 and blocks 1024 -> 2048. At ITERS=8, regs=34
// proved ptxas could not keep 8 float4 resident (interleaved loads, MLP<8)
// and the 16-point serial chain + 6.92 CTA/SM imbalance held occ at 59%.
// ITERS=4 = 16 data regs: genuinely front-batchable; 2x threads, half the
// chain length, finer CTA granularity for tail balance.

#define CX 640.0f
#define CY 480.0f

#define XTHREADS 256

struct KParams { float k0, k1, k2, k3, k4, rfx, rfy; };

__device__ __forceinline__ KParams load_params(const float* kvec,
                                               const float* fx_p,
                                               const float* fy_p)
{
    KParams P;
    P.k0 = __ldg(&kvec[0]); P.k1 = __ldg(&kvec[1]); P.k2 = __ldg(&kvec[2]);
    P.k3 = __ldg(&kvec[3]); P.k4 = __ldg(&kvec[4]);
    P.rfx = __fdividef(1.0f, __ldg(fx_p));
    P.rfy = __fdividef(1.0f, __ldg(fy_p));
    return P;
}

__device__ __forceinline__ float2 kb_point(float px, float py, const KParams& P)
{
    float dx = px - CX;
    float dy = py - CY;
    float mx = dx * P.rfx;
    float my = dy * P.rfy;
    float q  = fmaf(mx, mx, fmaf(my, my, 1e-30f));
    float ru = q * rsqrtf(q);

    float t = ru;
#pragma unroll
    for (int it = 0; it < 2; ++it) {
        float p = ((((P.k4 * t + P.k3) * t + P.k2) * t + P.k1) * t + P.k0);
        float r = fmaf(p, t, -ru);
        t = t - r;
    }

    float t2 = t * t;
    float w = fmaf(t2, fmaf(t2, fmaf(t2, fmaf(t2, 2.7557319e-6f, -1.9841270e-4f),
                                     8.3333333e-3f), -1.6666667e-1f), 1.0f);

    return make_float2(fmaf(w, dx, CX), fmaf(w, dy, CY));
}

// ---- specialized: n_pairs == gridDim.x * XTHREADS * ITERS exactly ----
template <int ITERS>
__global__ void __launch_bounds__(XTHREADS)
kb_exact_kernel(const float4* __restrict__ in4,
                const float*  __restrict__ kvec,
                const float*  __restrict__ fx_p,
                const float*  __restrict__ fy_p,
                float4*       __restrict__ out4)
{
    const int stride = gridDim.x * XTHREADS;        // uniform across block
    const int base   = blockIdx.x * XTHREADS + threadIdx.x;
    const KParams P  = load_params(kvec, fx_p, fy_p);

    float4 v[ITERS];
#pragma unroll
    for (int k = 0; k < ITERS; ++k)
        v[k] = in4[base + k * stride];              // ITERS independent LDG.128

#pragma unroll
    for (int k = 0; k < ITERS; ++k) {
        float2 a = kb_point(v[k].x, v[k].y, P);
        float2 b = kb_point(v[k].z, v[k].w, P);
        out4[base + k * stride] = make_float4(a.x, a.y, b.x, b.y);
    }
}

// ---- generic fallback ----
__global__ void __launch_bounds__(256)
kb_generic_kernel(const float4* __restrict__ in4,
                  const float2* __restrict__ in2,
                  const float*  __restrict__ kvec,
                  const float*  __restrict__ fx_p,
                  const float*  __restrict__ fy_p,
                  float4*       __restrict__ out4,
                  float2*       __restrict__ out2,
                  int n_pairs, int n_tail_pts)
{
    const int stride = gridDim.x * blockDim.x;
    int i = blockIdx.x * blockDim.x + threadIdx.x;
    const KParams P = load_params(kvec, fx_p, fy_p);

    for (; i < n_pairs; i += stride) {
        float4 p = in4[i];
        float2 a = kb_point(p.x, p.y, P);
        float2 b = kb_point(p.z, p.w, P);
        out4[i] = make_float4(a.x, a.y, b.x, b.y);
    }

    if (n_tail_pts && blockIdx.x == 0 && threadIdx.x == 0) {
        for (int j = 0; j < n_tail_pts; ++j) {
            int idx = 2 * n_pairs + j;
            float2 p = in2[idx];
            out2[idx] = kb_point(p.x, p.y, P);
        }
    }
}

extern "C" void kernel_launch(void* const* d_in, const int* in_sizes, int n_in,
                              void* d_out, int out_size)
{
    const float* uv = (const float*)d_in[0];   // [N,2] fp32
    const float* kv = (const float*)d_in[1];   // k_vector [5]
    const float* fx = (const float*)d_in[2];
    const float* fy = (const float*)d_in[3];

    int n       = in_sizes[0] / 2;
    int n_pairs = n / 2;
    int n_tail  = n - 2 * n_pairs;

    const int ITERS = 4;
    if (n_tail == 0 && n_pairs % (XTHREADS * ITERS) == 0) {
        // bench shape: N = 4194304 -> n_pairs = 2^21 = 2048 * 256 * 4
        int blocks = n_pairs / (XTHREADS * ITERS);
        kb_exact_kernel<ITERS><<<blocks, XTHREADS>>>(
            (const float4*)uv, kv, fx, fy, (float4*)d_out);
    } else {
        const int threads = 256;
        int blocks = 148 * 8;
        int need   = (n_pairs + threads - 1) / threads;
        if (need < blocks) blocks = need > 0 ? need : 1;
        kb_generic_kernel<<<blocks, threads>>>(
            (const float4*)uv, (const float2*)uv, kv, fx, fy,
            (float4*)d_out, (float2*)d_out, n_pairs, n_tail);
    }
}